// round 4
// baseline (speedup 1.0000x reference)
#include <cuda_runtime.h>
#include <cstdint>

// ---------------- problem constants ----------------
#define B_    16
#define N_    4096
#define CIN_  64
#define COUT_ 128
#define K_    16
#define M_    1024
#define EPS_  1e-5f

// ---------------- static device scratch ----------------
__device__ int   g_fps[B_ * M_];
__device__ float g_h[(size_t)B_ * N_ * COUT_];          // 32 MB
__device__ float g_ps[1024 * COUT_];
__device__ float g_ps2[1024 * COUT_];
__device__ float g_scale[COUT_];
__device__ float g_shift[COUT_];
__device__ float g_kk[B_ * N_];
__device__ float g_d2[(size_t)B_ * M_ * N_];            // 256 MB
__device__ int   g_nbr[B_ * M_ * K_];

// =====================================================================
// 1) Farthest point sampling: one block per batch, 256 threads, 16 pts/thread.
//    Distance formula kept non-contracted to match the reference exactly.
// =====================================================================
__global__ void __launch_bounds__(256) fps_kernel(const float* __restrict__ pos)
{
    extern __shared__ float sm[];
    float* sp = sm;                                              // [N_*3]
    unsigned long long* sred = (unsigned long long*)(sm + 3 * N_);  // [8]
    int* swidx = (int*)(sred + 8);

    const int b = blockIdx.x;
    const int t = threadIdx.x;
    const float* pb = pos + (size_t)b * N_ * 3;

    // stage positions into smem (float4 coalesced; 12288 floats = 3072 float4)
    for (int i = t; i < (3 * N_) / 4; i += 256)
        ((float4*)sp)[i] = ((const float4*)pb)[i];
    __syncthreads();

    const int FPT = 16;
    const int base = t * FPT;
    float px[16], py[16], pz[16], mind[16];
#pragma unroll
    for (int j = 0; j < FPT; j++) {
        px[j] = sp[(base + j) * 3 + 0];
        py[j] = sp[(base + j) * 3 + 1];
        pz[j] = sp[(base + j) * 3 + 2];
        mind[j] = 1e10f;
    }

    int widx = 0;
    if (t == 0) g_fps[b * M_] = 0;

    for (int m = 1; m < M_; m++) {
        const float qx = sp[widx * 3 + 0];
        const float qy = sp[widx * 3 + 1];
        const float qz = sp[widx * 3 + 2];

        float bv = -1.0f;
        int   bi = 0;
#pragma unroll
        for (int j = 0; j < FPT; j++) {
            // exact (non-FMA) form: (dx*dx + dy*dy) + dz*dz
            float dx = __fsub_rn(px[j], qx);
            float dy = __fsub_rn(py[j], qy);
            float dz = __fsub_rn(pz[j], qz);
            float s  = __fadd_rn(__fadd_rn(__fmul_rn(dx, dx), __fmul_rn(dy, dy)),
                                 __fmul_rn(dz, dz));
            float md = fminf(mind[j], s);
            mind[j] = md;
            if (md > bv) { bv = md; bi = base + j; }   // strict > keeps lowest idx
        }

        // pack: value bits high (d >= 0, monotone), inverted index low (tie -> lower idx)
        unsigned long long p =
            ((unsigned long long)__float_as_uint(bv) << 32) | (unsigned)(N_ - 1 - bi);
#pragma unroll
        for (int o = 16; o > 0; o >>= 1) {
            unsigned long long q = __shfl_down_sync(0xffffffffu, p, o);
            p = (q > p) ? q : p;
        }
        if ((t & 31) == 0) sred[t >> 5] = p;
        __syncthreads();
        if (t == 0) {
            unsigned long long r = sred[0];
#pragma unroll
            for (int w = 1; w < 8; w++) r = (sred[w] > r) ? sred[w] : r;
            int wi = N_ - 1 - (int)(unsigned)(r & 0xffffffffu);
            *swidx = wi;
            g_fps[b * M_ + m] = wi;
        }
        __syncthreads();
        widx = *swidx;
    }
}

// =====================================================================
// 2) Linear (features @ W + b) -> g_h, with per-block partial sums for BN stats.
//    Block = 64 points, thread = output channel. W column held in registers.
// =====================================================================
__global__ void __launch_bounds__(128) linear_kernel(const float* __restrict__ feat,
                                                     const float* __restrict__ W,
                                                     const float* __restrict__ bias)
{
    __shared__ float4 fs[64 * 16];   // 64 points x 64 dims (as 16 float4 each)
    const int o   = threadIdx.x;
    const int blk = blockIdx.x;
    const size_t p0 = (size_t)blk * 64;

    float w[64];
#pragma unroll
    for (int c = 0; c < 64; c++) w[c] = W[c * COUT_ + o];
    const float bo = bias[o];

    const float4* fg = (const float4*)(feat + p0 * CIN_);
#pragma unroll
    for (int i = 0; i < 8; i++) fs[o + i * 128] = fg[o + i * 128];
    __syncthreads();

    float s1 = 0.f, s2 = 0.f;
    for (int p = 0; p < 64; p++) {
        float acc = bo;
#pragma unroll
        for (int cq = 0; cq < 16; cq++) {
            float4 v = fs[p * 16 + cq];
            acc = fmaf(v.x, w[cq * 4 + 0], acc);
            acc = fmaf(v.y, w[cq * 4 + 1], acc);
            acc = fmaf(v.z, w[cq * 4 + 2], acc);
            acc = fmaf(v.w, w[cq * 4 + 3], acc);
        }
        g_h[(p0 + p) * COUT_ + o] = acc;
        s1 += acc;
        s2 = fmaf(acc, acc, s2);
    }
    g_ps [blk * COUT_ + o] = s1;
    g_ps2[blk * COUT_ + o] = s2;
}

// =====================================================================
// 3) Finalize BN stats -> scale/shift per channel.
// =====================================================================
__global__ void __launch_bounds__(256) stats_kernel(const float* __restrict__ gamma,
                                                    const float* __restrict__ beta)
{
    const int c = blockIdx.x;
    const int t = threadIdx.x;
    float s1 = 0.f, s2 = 0.f;
    for (int i = t; i < 1024; i += 256) {
        s1 += g_ps [i * COUT_ + c];
        s2 += g_ps2[i * COUT_ + c];
    }
    __shared__ float r1[256], r2[256];
    r1[t] = s1; r2[t] = s2;
    __syncthreads();
    for (int o = 128; o > 0; o >>= 1) {
        if (t < o) { r1[t] += r1[t + o]; r2[t] += r2[t + o]; }
        __syncthreads();
    }
    if (t == 0) {
        const float inv = 1.0f / (float)(B_ * N_);
        float mean = r1[0] * inv;
        float var  = r2[0] * inv - mean * mean;
        float sc   = gamma[c] * rsqrtf(var + EPS_);
        g_scale[c] = sc;
        g_shift[c] = beta[c] - mean * sc;
    }
}

// =====================================================================
// 4) Per-key squared feature norms.
// =====================================================================
__global__ void __launch_bounds__(256) kk_kernel(const float* __restrict__ feat)
{
    const int r = blockIdx.x * 256 + threadIdx.x;     // 65536 rows
    const float4* f = (const float4*)(feat + (size_t)r * CIN_);
    float s = 0.f;
#pragma unroll
    for (int i = 0; i < 16; i++) {
        float4 v = f[i];
        s = fmaf(v.x, v.x, s);
        s = fmaf(v.y, v.y, s);
        s = fmaf(v.z, v.z, s);
        s = fmaf(v.w, v.w, s);
    }
    g_kk[r] = s;
}

// =====================================================================
// 5) kNN distance GEMM: d2'[b,m,n] = kk[n] - 2 * <q_m, f_n>  (|q|^2 dropped:
//    constant per row, cannot change per-row top-k ordering).
//    128x128 tile per block, Kdim=64 fully staged, 8x8 register tiles.
// =====================================================================
__global__ void __launch_bounds__(256) gemm_kernel(const float* __restrict__ feat)
{
    extern __shared__ float smg[];
    float* Qs = smg;                 // [64][128] d-major
    float* Fs = smg + 64 * 128;      // [64][128] d-major
    __shared__ int qrow[128];

    const int b  = blockIdx.z;
    const int mt = blockIdx.y;
    const int nt = blockIdx.x;
    const int t  = threadIdx.x;
    const float* fb = feat + (size_t)b * N_ * CIN_;

    if (t < 128) qrow[t] = g_fps[b * M_ + mt * 128 + t];
    __syncthreads();

    {   // staging: 2 threads per row, 8 float4 each, transposed write
        const int row  = t >> 1;
        const int half = (t & 1) * 8;
        const float4* srcQ = (const float4*)(fb + (size_t)qrow[row] * CIN_);
        const float4* srcF = (const float4*)(fb + (size_t)(nt * 128 + row) * CIN_);
#pragma unroll
        for (int i = 0; i < 8; i++) {
            float4 v = srcQ[half + i];
            int d = (half + i) * 4;
            Qs[(d + 0) * 128 + row] = v.x;
            Qs[(d + 1) * 128 + row] = v.y;
            Qs[(d + 2) * 128 + row] = v.z;
            Qs[(d + 3) * 128 + row] = v.w;
        }
#pragma unroll
        for (int i = 0; i < 8; i++) {
            float4 v = srcF[half + i];
            int d = (half + i) * 4;
            Fs[(d + 0) * 128 + row] = v.x;
            Fs[(d + 1) * 128 + row] = v.y;
            Fs[(d + 2) * 128 + row] = v.z;
            Fs[(d + 3) * 128 + row] = v.w;
        }
    }
    __syncthreads();

    const int tx = t & 15, ty = t >> 4;
    const int n0 = tx * 8, m0 = ty * 8;

    float acc[8][8];
#pragma unroll
    for (int i = 0; i < 8; i++)
#pragma unroll
        for (int j = 0; j < 8; j++) acc[i][j] = 0.f;

#pragma unroll 4
    for (int d = 0; d < 64; d++) {
        float4 qa  = *(const float4*)&Qs[d * 128 + m0];
        float4 qb  = *(const float4*)&Qs[d * 128 + m0 + 4];
        float4 fa  = *(const float4*)&Fs[d * 128 + n0];
        float4 fb4 = *(const float4*)&Fs[d * 128 + n0 + 4];
        float qv[8] = {qa.x, qa.y, qa.z, qa.w, qb.x, qb.y, qb.z, qb.w};
        float fv[8] = {fa.x, fa.y, fa.z, fa.w, fb4.x, fb4.y, fb4.z, fb4.w};
#pragma unroll
        for (int i = 0; i < 8; i++)
#pragma unroll
            for (int j = 0; j < 8; j++)
                acc[i][j] = fmaf(qv[i], fv[j], acc[i][j]);
    }

    float kkv[8];
#pragma unroll
    for (int j = 0; j < 8; j++) kkv[j] = g_kk[b * N_ + nt * 128 + n0 + j];

    float* out = g_d2 + ((size_t)(b * M_ + mt * 128 + m0)) * N_ + nt * 128 + n0;
#pragma unroll
    for (int i = 0; i < 8; i++) {
        float4 o1, o2;
        o1.x = fmaf(acc[i][0], -2.f, kkv[0]);
        o1.y = fmaf(acc[i][1], -2.f, kkv[1]);
        o1.z = fmaf(acc[i][2], -2.f, kkv[2]);
        o1.w = fmaf(acc[i][3], -2.f, kkv[3]);
        o2.x = fmaf(acc[i][4], -2.f, kkv[4]);
        o2.y = fmaf(acc[i][5], -2.f, kkv[5]);
        o2.z = fmaf(acc[i][6], -2.f, kkv[6]);
        o2.w = fmaf(acc[i][7], -2.f, kkv[7]);
        *(float4*)(out + (size_t)i * N_)     = o1;
        *(float4*)(out + (size_t)i * N_ + 4) = o2;
    }
}

// =====================================================================
// 6) top-K=16 smallest per row (16 argmin passes over smem row).
//    Sortable-uint packing handles negative d2'; ties -> lower index.
// =====================================================================
__global__ void __launch_bounds__(256) topk_kernel()
{
    __shared__ float row[N_];
    __shared__ unsigned long long sred[8];

    const int q = blockIdx.x;                 // b*M + m
    const int t = threadIdx.x;
    const float4* src = (const float4*)(g_d2 + (size_t)q * N_);
#pragma unroll
    for (int i = 0; i < 4; i++) ((float4*)row)[t + i * 256] = src[t + i * 256];
    __syncthreads();

    for (int k = 0; k < K_; k++) {
        unsigned long long best = 0xFFFFFFFFFFFFFFFFULL;
#pragma unroll
        for (int i = 0; i < 16; i++) {
            int idx = t + i * 256;
            unsigned u = __float_as_uint(row[idx]);
            u ^= (unsigned)((int)u >> 31) | 0x80000000u;   // float -> sortable uint
            unsigned long long p = ((unsigned long long)u << 32) | (unsigned)idx;
            best = (p < best) ? p : best;
        }
#pragma unroll
        for (int o = 16; o > 0; o >>= 1) {
            unsigned long long v = __shfl_down_sync(0xffffffffu, best, o);
            best = (v < best) ? v : best;
        }
        if ((t & 31) == 0) sred[t >> 5] = best;
        __syncthreads();
        if (t == 0) {
            unsigned long long r = sred[0];
#pragma unroll
            for (int w = 1; w < 8; w++) r = (sred[w] < r) ? sred[w] : r;
            int wi = (int)(unsigned)(r & 0xffffffffu);
            g_nbr[q * K_ + k] = wi;
            row[wi] = __int_as_float(0x7f800000);          // +inf, exclude
        }
        __syncthreads();
    }
}

// =====================================================================
// 7) Gather + BN-folded max-pool + positions/batch outputs.
//    max_k(s*h+t) = s*max(h)+t if s>=0 else s*min(h)+t.
// =====================================================================
__global__ void __launch_bounds__(128) gather_kernel(const float* __restrict__ pos,
                                                     float* __restrict__ out)
{
    const size_t OFF_POS   = (size_t)B_ * M_ * COUT_;            // 2097152
    const size_t OFF_BATCH = OFF_POS + (size_t)B_ * M_ * 3;      // 2146304

    const int q = blockIdx.x;        // b*M + m
    const int b = q >> 10;           // M_ = 1024
    const int c = threadIdx.x;

    __shared__ int sn[K_];
    if (c < K_) sn[c] = g_nbr[q * K_ + c];
    __syncthreads();

    const float* hb = g_h + (size_t)b * N_ * COUT_;
    float mx = -__int_as_float(0x7f800000);
    float mn =  __int_as_float(0x7f800000);
#pragma unroll
    for (int k = 0; k < K_; k++) {
        float v = hb[(size_t)sn[k] * COUT_ + c];
        mx = fmaxf(mx, v);
        mn = fminf(mn, v);
    }
    const float s = g_scale[c];
    out[(size_t)q * COUT_ + c] = fmaf(s, (s >= 0.f) ? mx : mn, g_shift[c]);

    if (c < 3) {
        int fi = g_fps[q];
        out[OFF_POS + (size_t)q * 3 + c] = pos[((size_t)b * N_ + fi) * 3 + c];
    }
    if (c == 3) out[OFF_BATCH + q] = (float)b;
}

// =====================================================================
// launch
// =====================================================================
extern "C" void kernel_launch(void* const* d_in, const int* in_sizes, int n_in,
                              void* d_out, int out_size)
{
    const float* features  = (const float*)d_in[0];
    const float* positions = (const float*)d_in[1];
    // d_in[2] = batch (int64): values are deterministic (b), unused
    const float* W     = (const float*)d_in[3];
    const float* bias  = (const float*)d_in[4];
    const float* gamma = (const float*)d_in[5];
    const float* beta  = (const float*)d_in[6];
    float* out = (float*)d_out;

    const int fps_smem  = 3 * N_ * 4 + 8 * 8 + 16;   // ~49.3 KB
    const int gemm_smem = 2 * 64 * 128 * 4;          // 64 KB
    cudaFuncSetAttribute(fps_kernel,  cudaFuncAttributeMaxDynamicSharedMemorySize, fps_smem);
    cudaFuncSetAttribute(gemm_kernel, cudaFuncAttributeMaxDynamicSharedMemorySize, gemm_smem);

    fps_kernel<<<B_, 256, fps_smem>>>(positions);
    linear_kernel<<<(B_ * N_) / 64, 128>>>(features, W, bias);
    stats_kernel<<<COUT_, 256>>>(gamma, beta);
    kk_kernel<<<(B_ * N_) / 256, 256>>>(features);
    gemm_kernel<<<dim3(N_ / 128, M_ / 128, B_), 256, gemm_smem>>>(features);
    topk_kernel<<<B_ * M_, 256>>>();
    gather_kernel<<<B_ * M_, 128>>>(positions, out);
}